// round 2
// baseline (speedup 1.0000x reference)
#include <cuda_runtime.h>
#include <math.h>

#define NB 2048
#define NC 100
#define NK 8
#define ND 64
#define NCK 800
#define CKP 832
#define NPAIR 2080
#define PDIM 2145
#define PPAD 2176

__device__ __align__(128) float g_At[PPAD * CKP];
__device__ __align__(128) float g_Gt[PPAD * NB];
__device__ __align__(128) float g_cls[NB * NC];

// ---- Kernel 1: per-(c,k) prep: invert L, build packed A / linear / const rows
__global__ void prep_kernel(const float* __restrict__ mix,
                            const float* __restrict__ loc,
                            const float* __restrict__ tril) {
    const int ck = blockIdx.x, tid = threadIdx.x;
    if (ck >= NCK) {
        for (int p = tid; p < PPAD; p += 64) g_At[p * CKP + ck] = 0.0f;
        return;
    }
    const int c = ck >> 3, k = ck & 7;
    __shared__ float Lsh[ND][65];
    __shared__ float rowbuf[ND], locsh[ND], vsh[ND], red[ND];
    __shared__ int rs[ND + 1];

    const float* Lg = tril + (size_t)ck * ND * ND;
    for (int idx = tid; idx < ND * ND; idx += 64) Lsh[idx >> 6][idx & 63] = Lg[idx];
    locsh[tid] = loc[ck * ND + tid];
    rs[tid] = tid * ND - tid * (tid - 1) / 2;
    if (tid == 0) rs[ND] = NPAIR;
    __syncthreads();
    const float mydiag = Lsh[tid][tid];

    // in-place forward substitution: rows become M = L^{-1}
    for (int i = 0; i < ND; ++i) {
        rowbuf[tid] = Lsh[i][tid];
        __syncthreads();
        float nv = 0.0f;
        if (tid <= i) {
            float s = (tid == i) ? 1.0f : 0.0f;
            for (int t = tid; t < i; ++t) s -= rowbuf[t] * Lsh[t][tid];
            nv = s / rowbuf[i];
        }
        Lsh[i][tid] = nv;
        __syncthreads();
    }

    float vd = 0.0f;                                  // v = M*mu
    for (int t = 0; t <= tid; ++t) vd += Lsh[tid][t] * locsh[t];
    vsh[tid] = vd;
    __syncthreads();
    float wd = 0.0f;                                  // w = M^T v = A*mu
    for (int t = tid; t < ND; ++t) wd += Lsh[t][tid] * vsh[t];
    g_At[(NPAIR + tid) * CKP + ck] = -2.0f * wd;

    red[tid] = vd * vd;  __syncthreads();
    for (int o = 32; o > 0; o >>= 1) { if (tid < o) red[tid] += red[tid + o]; __syncthreads(); }
    const float cst = red[0];  __syncthreads();
    red[tid] = logf(fabsf(mydiag));  __syncthreads();
    for (int o = 32; o > 0; o >>= 1) { if (tid < o) red[tid] += red[tid + o]; __syncthreads(); }
    const float logdet = red[0];

    float ml[NK], mmx = -1e30f;
    #pragma unroll
    for (int kk = 0; kk < NK; ++kk) { ml[kk] = mix[c * NK + kk]; mmx = fmaxf(mmx, ml[kk]); }
    float msum = 0.0f;
    #pragma unroll
    for (int kk = 0; kk < NK; ++kk) msum += expf(ml[kk] - mmx);
    const float mixlog = ml[k] - (mmx + logf(msum));
    const float bias = -0.5f * cst - 32.0f * 1.8378770664093454836f - logdet + mixlog;
    if (tid == 0) g_At[2144 * CKP + ck] = -2.0f * bias;
    for (int p = PDIM + tid; p < PPAD; p += 64) g_At[p * CKP + ck] = 0.0f;

    int i = 0;                                        // packed A = M^T M
    for (int p = tid; p < NPAIR; p += 64) {
        while (rs[i + 1] <= p) ++i;
        const int j = i + (p - rs[i]);
        float s = 0.0f;
        for (int t = j; t < ND; ++t) s += Lsh[t][i] * Lsh[t][j];
        g_At[p * CKP + ck] = (i == j) ? s : 2.0f * s;
    }
}

// ---- Kernel 2: G^T [p][b]: x_i*x_j rows, x_d rows, const row, zero pad
__global__ void gbuild_kernel(const float* __restrict__ rep) {
    __shared__ float xs[ND * 129];
    const int bt = blockIdx.x, i = blockIdx.y, tid = threadIdx.x;
    for (int f = tid; f < 128 * ND; f += 128) {
        const int b = f >> 6, d = f & 63;
        xs[d * 129 + b] = rep[(bt * 128 + b) * ND + d];
    }
    __syncthreads();
    const int b = bt * 128 + tid;
    const int rsI = i * ND - i * (i - 1) / 2;
    const float xi = xs[i * 129 + tid];
    for (int j = i; j < ND; ++j)
        g_Gt[(rsI + j - i) * NB + b] = xi * xs[j * 129 + tid];
    if (i == 0) {
        #pragma unroll 4
        for (int d = 0; d < ND; ++d) g_Gt[(NPAIR + d) * NB + b] = xs[d * 129 + tid];
        g_Gt[2144 * NB + b] = 1.0f;
        for (int p = PDIM; p < PPAD; ++p) g_Gt[p * NB + b] = 0.0f;
    }
}

// ---- Kernel 3: fp32 GEMM (-0.5 * Gt^T @ At) + fused logsumexp over k
#define BM 64
#define BN 64
#define KS 16
#define NSLICE (PPAD / KS)

__device__ __forceinline__ void cp16(float* s, const float* g) {
    unsigned a = (unsigned)__cvta_generic_to_shared(s);
    asm volatile("cp.async.cg.shared.global [%0], [%1], 16;\n" :: "r"(a), "l"(g));
}

__global__ void __launch_bounds__(128) gemm_kernel() {
    __shared__ __align__(16) float Gs[2][KS][BM];
    __shared__ __align__(16) float As[2][KS][BN];
    const int tid = threadIdx.x;
    const int bm0 = blockIdx.x * BM, bn0 = blockIdx.y * BN;
    const int tx = tid & 15, ty = tid >> 4;

    float acc[8][4];
    #pragma unroll
    for (int m = 0; m < 8; ++m)
        #pragma unroll
        for (int n = 0; n < 4; ++n) acc[m][n] = 0.0f;

    #pragma unroll
    for (int q = 0; q < 2; ++q) {
        const int f = tid + 128 * q, r = f >> 4, cc = (f & 15) * 4;
        cp16(&Gs[0][r][cc], g_Gt + r * NB + bm0 + cc);
        cp16(&As[0][r][cc], g_At + r * CKP + bn0 + cc);
    }
    asm volatile("cp.async.commit_group;\n" ::: "memory");

    for (int s = 0; s < NSLICE; ++s) {
        const int buf = s & 1;
        if (s + 1 < NSLICE) {
            const int p0 = (s + 1) * KS, nb = buf ^ 1;
            #pragma unroll
            for (int q = 0; q < 2; ++q) {
                const int f = tid + 128 * q, r = f >> 4, cc = (f & 15) * 4;
                cp16(&Gs[nb][r][cc], g_Gt + (p0 + r) * NB + bm0 + cc);
                cp16(&As[nb][r][cc], g_At + (p0 + r) * CKP + bn0 + cc);
            }
            asm volatile("cp.async.commit_group;\n" ::: "memory");
            asm volatile("cp.async.wait_group 1;\n" ::: "memory");
        } else {
            asm volatile("cp.async.wait_group 0;\n" ::: "memory");
        }
        __syncthreads();
        #pragma unroll
        for (int kk = 0; kk < KS; ++kk) {
            const float4 gA = *reinterpret_cast<const float4*>(&Gs[buf][kk][ty * 8]);
            const float4 gB = *reinterpret_cast<const float4*>(&Gs[buf][kk][ty * 8 + 4]);
            const float4 aa = *reinterpret_cast<const float4*>(&As[buf][kk][tx * 4]);
            const float gv[8] = {gA.x, gA.y, gA.z, gA.w, gB.x, gB.y, gB.z, gB.w};
            const float av[4] = {aa.x, aa.y, aa.z, aa.w};
            #pragma unroll
            for (int m = 0; m < 8; ++m)
                #pragma unroll
                for (int n = 0; n < 4; ++n)
                    acc[m][n] = fmaf(gv[m], av[n], acc[m][n]);
        }
        __syncthreads();
    }

    const int c = bn0 / 8 + (tx >> 1);
    const bool store = ((tx & 1) == 0) && (c < NC);
    #pragma unroll
    for (int m = 0; m < 8; ++m) {
        const float s0 = -0.5f * acc[m][0], s1 = -0.5f * acc[m][1];
        const float s2 = -0.5f * acc[m][2], s3 = -0.5f * acc[m][3];
        float mx = fmaxf(fmaxf(s0, s1), fmaxf(s2, s3));
        float se = expf(s0 - mx) + expf(s1 - mx) + expf(s2 - mx) + expf(s3 - mx);
        const float pm = __shfl_xor_sync(0xffffffffu, mx, 1);
        const float ps = __shfl_xor_sync(0xffffffffu, se, 1);
        const float M2 = fmaxf(mx, pm);
        const float tot = se * expf(mx - M2) + ps * expf(pm - M2);
        if (store) g_cls[(bm0 + ty * 8 + m) * NC + c] = M2 + logf(tot);
    }
}

// ---- Kernel 4: row log_softmax over C=100 (one warp per row)
__global__ void softmax_kernel(float* __restrict__ out) {
    const int lane = threadIdx.x & 31;
    const int b = blockIdx.x * 8 + (threadIdx.x >> 5);
    float v[4];
    float mx = -INFINITY;
    #pragma unroll
    for (int q = 0; q < 4; ++q) {
        const int cc = lane + 32 * q;
        v[q] = (cc < NC) ? g_cls[b * NC + cc] : -INFINITY;
        mx = fmaxf(mx, v[q]);
    }
    #pragma unroll
    for (int o = 16; o > 0; o >>= 1) mx = fmaxf(mx, __shfl_xor_sync(0xffffffffu, mx, o));
    float sum = 0.0f;
    #pragma unroll
    for (int q = 0; q < 4; ++q) {
        const int cc = lane + 32 * q;
        if (cc < NC) sum += expf(v[q] - mx);
    }
    #pragma unroll
    for (int o = 16; o > 0; o >>= 1) sum += __shfl_xor_sync(0xffffffffu, sum, o);
    const float lse = mx + logf(sum);
    #pragma unroll
    for (int q = 0; q < 4; ++q) {
        const int cc = lane + 32 * q;
        if (cc < NC) out[b * NC + cc] = v[q] - lse;
    }
}

extern "C" void kernel_launch(void* const* d_in, const int* in_sizes, int n_in,
                              void* d_out, int out_size) {
    const float *rep = nullptr, *mix = nullptr, *loc = nullptr, *tril = nullptr;
    for (int i = 0; i < n_in; ++i) {
        switch (in_sizes[i]) {
            case NB * ND:       rep  = (const float*)d_in[i]; break;
            case NC * NK:       mix  = (const float*)d_in[i]; break;
            case NCK * ND:      loc  = (const float*)d_in[i]; break;
            case NCK * ND * ND: tril = (const float*)d_in[i]; break;
            default: break;
        }
    }
    if (!rep || !mix || !loc || !tril) {   // positional fallback (reference order)
        rep  = (const float*)d_in[0];
        mix  = (const float*)d_in[1];
        loc  = (const float*)d_in[2];
        tril = (const float*)d_in[3];
    }
    prep_kernel<<<CKP, 64>>>(mix, loc, tril);
    gbuild_kernel<<<dim3(NB / 128, ND), 128>>>(rep);
    gemm_kernel<<<dim3(NB / BM, CKP / BN), 128>>>();
    softmax_kernel<<<NB / 8, 256>>>((float*)d_out);
}

// round 3
// speedup vs baseline: 1.6258x; 1.6258x over previous
#include <cuda_runtime.h>
#include <math.h>

#define NB 2048
#define NC 100
#define NK 8
#define ND 64
#define NCK 800
#define CKP 832
#define NPAIR 2080
#define PDIM 2145
#define PPAD 2176

__device__ __align__(128) float g_At[PPAD * CKP];
__device__ __align__(128) float g_Gt[PPAD * NB];
__device__ __align__(128) float g_cls[NB * NC];

// ---- Kernel 1: per-(c,k) prep: invert L, build packed A / linear / const rows
__global__ void prep_kernel(const float* __restrict__ mix,
                            const float* __restrict__ loc,
                            const float* __restrict__ tril) {
    const int ck = blockIdx.x, tid = threadIdx.x;
    if (ck >= NCK) {
        for (int p = tid; p < PPAD; p += 64) g_At[p * CKP + ck] = 0.0f;
        return;
    }
    const int c = ck >> 3, k = ck & 7;
    __shared__ float Lsh[ND][65];
    __shared__ float rowbuf[ND], locsh[ND], vsh[ND], red[ND];
    __shared__ int rs[ND + 1];

    const float* Lg = tril + (size_t)ck * ND * ND;
    for (int idx = tid; idx < ND * ND; idx += 64) Lsh[idx >> 6][idx & 63] = Lg[idx];
    locsh[tid] = loc[ck * ND + tid];
    rs[tid] = tid * ND - tid * (tid - 1) / 2;
    if (tid == 0) rs[ND] = NPAIR;
    __syncthreads();
    const float mydiag = Lsh[tid][tid];

    // in-place forward substitution: rows become M = L^{-1}
    for (int i = 0; i < ND; ++i) {
        rowbuf[tid] = Lsh[i][tid];
        __syncthreads();
        float nv = 0.0f;
        if (tid <= i) {
            float s = (tid == i) ? 1.0f : 0.0f;
            for (int t = tid; t < i; ++t) s -= rowbuf[t] * Lsh[t][tid];
            nv = s / rowbuf[i];
        }
        Lsh[i][tid] = nv;
        __syncthreads();
    }

    float vd = 0.0f;                                  // v = M*mu
    for (int t = 0; t <= tid; ++t) vd += Lsh[tid][t] * locsh[t];
    vsh[tid] = vd;
    __syncthreads();
    float wd = 0.0f;                                  // w = M^T v = A*mu
    for (int t = tid; t < ND; ++t) wd += Lsh[t][tid] * vsh[t];
    g_At[(NPAIR + tid) * CKP + ck] = -2.0f * wd;

    red[tid] = vd * vd;  __syncthreads();
    for (int o = 32; o > 0; o >>= 1) { if (tid < o) red[tid] += red[tid + o]; __syncthreads(); }
    const float cst = red[0];  __syncthreads();
    red[tid] = logf(fabsf(mydiag));  __syncthreads();
    for (int o = 32; o > 0; o >>= 1) { if (tid < o) red[tid] += red[tid + o]; __syncthreads(); }
    const float logdet = red[0];

    float ml[NK], mmx = -1e30f;
    #pragma unroll
    for (int kk = 0; kk < NK; ++kk) { ml[kk] = mix[c * NK + kk]; mmx = fmaxf(mmx, ml[kk]); }
    float msum = 0.0f;
    #pragma unroll
    for (int kk = 0; kk < NK; ++kk) msum += expf(ml[kk] - mmx);
    const float mixlog = ml[k] - (mmx + logf(msum));
    const float bias = -0.5f * cst - 32.0f * 1.8378770664093454836f - logdet + mixlog;
    if (tid == 0) g_At[2144 * CKP + ck] = -2.0f * bias;
    for (int p = PDIM + tid; p < PPAD; p += 64) g_At[p * CKP + ck] = 0.0f;

    int i = 0;                                        // packed A = M^T M
    for (int p = tid; p < NPAIR; p += 64) {
        while (rs[i + 1] <= p) ++i;
        const int j = i + (p - rs[i]);
        float s = 0.0f;
        for (int t = j; t < ND; ++t) s += Lsh[t][i] * Lsh[t][j];
        g_At[p * CKP + ck] = (i == j) ? s : 2.0f * s;
    }
}

// ---- Kernel 2: G^T [p][b]: x_i*x_j rows, x_d rows, const row, zero pad
__global__ void gbuild_kernel(const float* __restrict__ rep) {
    __shared__ float xs[ND * 129];
    const int bt = blockIdx.x, i = blockIdx.y, tid = threadIdx.x;
    for (int f = tid; f < 128 * ND; f += 128) {
        const int b = f >> 6, d = f & 63;
        xs[d * 129 + b] = rep[(bt * 128 + b) * ND + d];
    }
    __syncthreads();
    const int b = bt * 128 + tid;
    const int rsI = i * ND - i * (i - 1) / 2;
    const float xi = xs[i * 129 + tid];
    for (int j = i; j < ND; ++j)
        g_Gt[(rsI + j - i) * NB + b] = xi * xs[j * 129 + tid];
    if (i == 0) {
        #pragma unroll 4
        for (int d = 0; d < ND; ++d) g_Gt[(NPAIR + d) * NB + b] = xs[d * 129 + tid];
        g_Gt[2144 * NB + b] = 1.0f;
        for (int p = PDIM; p < PPAD; ++p) g_Gt[p * NB + b] = 0.0f;
    }
}

// ---- Kernel 3: fp32 GEMM (-0.5 * Gt^T @ At) + fused logsumexp over k
#define BM 64
#define BN 64
#define KS 16
#define NSLICE (PPAD / KS)

__device__ __forceinline__ void cp16(float* s, const float* g) {
    unsigned a = (unsigned)__cvta_generic_to_shared(s);
    asm volatile("cp.async.cg.shared.global [%0], [%1], 16;\n" :: "r"(a), "l"(g));
}

__global__ void __launch_bounds__(128) gemm_kernel() {
    __shared__ __align__(16) float Gs[2][KS][BM];
    __shared__ __align__(16) float As[2][KS][BN];
    const int tid = threadIdx.x;
    const int bm0 = blockIdx.x * BM, bn0 = blockIdx.y * BN;
    const int tx = tid & 15, ty = tid >> 4;

    float acc[8][4];
    #pragma unroll
    for (int m = 0; m < 8; ++m)
        #pragma unroll
        for (int n = 0; n < 4; ++n) acc[m][n] = 0.0f;

    #pragma unroll
    for (int q = 0; q < 2; ++q) {
        const int f = tid + 128 * q, r = f >> 4, cc = (f & 15) * 4;
        cp16(&Gs[0][r][cc], g_Gt + r * NB + bm0 + cc);
        cp16(&As[0][r][cc], g_At + r * CKP + bn0 + cc);
    }
    asm volatile("cp.async.commit_group;\n" ::: "memory");

    for (int s = 0; s < NSLICE; ++s) {
        const int buf = s & 1;
        if (s + 1 < NSLICE) {
            const int p0 = (s + 1) * KS, nb = buf ^ 1;
            #pragma unroll
            for (int q = 0; q < 2; ++q) {
                const int f = tid + 128 * q, r = f >> 4, cc = (f & 15) * 4;
                cp16(&Gs[nb][r][cc], g_Gt + (p0 + r) * NB + bm0 + cc);
                cp16(&As[nb][r][cc], g_At + (p0 + r) * CKP + bn0 + cc);
            }
            asm volatile("cp.async.commit_group;\n" ::: "memory");
            asm volatile("cp.async.wait_group 1;\n" ::: "memory");
        } else {
            asm volatile("cp.async.wait_group 0;\n" ::: "memory");
        }
        __syncthreads();
        #pragma unroll
        for (int kk = 0; kk < KS; ++kk) {
            const float4 gA = *reinterpret_cast<const float4*>(&Gs[buf][kk][ty * 8]);
            const float4 gB = *reinterpret_cast<const float4*>(&Gs[buf][kk][ty * 8 + 4]);
            const float4 aa = *reinterpret_cast<const float4*>(&As[buf][kk][tx * 4]);
            const float gv[8] = {gA.x, gA.y, gA.z, gA.w, gB.x, gB.y, gB.z, gB.w};
            const float av[4] = {aa.x, aa.y, aa.z, aa.w};
            #pragma unroll
            for (int m = 0; m < 8; ++m)
                #pragma unroll
                for (int n = 0; n < 4; ++n)
                    acc[m][n] = fmaf(gv[m], av[n], acc[m][n]);
        }
        __syncthreads();
    }

    const int c = bn0 / 8 + (tx >> 1);
    const bool store = ((tx & 1) == 0) && (c < NC);
    #pragma unroll
    for (int m = 0; m < 8; ++m) {
        const float s0 = -0.5f * acc[m][0], s1 = -0.5f * acc[m][1];
        const float s2 = -0.5f * acc[m][2], s3 = -0.5f * acc[m][3];
        float mx = fmaxf(fmaxf(s0, s1), fmaxf(s2, s3));
        float se = expf(s0 - mx) + expf(s1 - mx) + expf(s2 - mx) + expf(s3 - mx);
        const float pm = __shfl_xor_sync(0xffffffffu, mx, 1);
        const float ps = __shfl_xor_sync(0xffffffffu, se, 1);
        const float M2 = fmaxf(mx, pm);
        const float tot = se * expf(mx - M2) + ps * expf(pm - M2);
        if (store) g_cls[(bm0 + ty * 8 + m) * NC + c] = M2 + logf(tot);
    }
}

// ---- Kernel 4: row log_softmax over C=100 (one warp per row)
__global__ void softmax_kernel(float* __restrict__ out) {
    const int lane = threadIdx.x & 31;
    const int b = blockIdx.x * 8 + (threadIdx.x >> 5);
    float v[4];
    float mx = -INFINITY;
    #pragma unroll
    for (int q = 0; q < 4; ++q) {
        const int cc = lane + 32 * q;
        v[q] = (cc < NC) ? g_cls[b * NC + cc] : -INFINITY;
        mx = fmaxf(mx, v[q]);
    }
    #pragma unroll
    for (int o = 16; o > 0; o >>= 1) mx = fmaxf(mx, __shfl_xor_sync(0xffffffffu, mx, o));
    float sum = 0.0f;
    #pragma unroll
    for (int q = 0; q < 4; ++q) {
        const int cc = lane + 32 * q;
        if (cc < NC) sum += expf(v[q] - mx);
    }
    #pragma unroll
    for (int o = 16; o > 0; o >>= 1) sum += __shfl_xor_sync(0xffffffffu, sum, o);
    const float lse = mx + logf(sum);
    #pragma unroll
    for (int q = 0; q < 4; ++q) {
        const int cc = lane + 32 * q;
        if (cc < NC) out[b * NC + cc] = v[q] - lse;
    }
}

extern "C" void kernel_launch(void* const* d_in, const int* in_sizes, int n_in,
                              void* d_out, int out_size) {
    const float *rep = nullptr, *mix = nullptr, *loc = nullptr, *tril = nullptr;
    for (int i = 0; i < n_in; ++i) {
        switch (in_sizes[i]) {
            case NB * ND:       rep  = (const float*)d_in[i]; break;
            case NC * NK:       mix  = (const float*)d_in[i]; break;
            case NCK * ND:      loc  = (const float*)d_in[i]; break;
            case NCK * ND * ND: tril = (const float*)d_in[i]; break;
            default: break;
        }
    }
    if (!rep || !mix || !loc || !tril) {   // positional fallback (reference order)
        rep  = (const float*)d_in[0];
        mix  = (const float*)d_in[1];
        loc  = (const float*)d_in[2];
        tril = (const float*)d_in[3];
    }
    prep_kernel<<<CKP, 64>>>(mix, loc, tril);
    gbuild_kernel<<<dim3(NB / 128, ND), 128>>>(rep);
    gemm_kernel<<<dim3(NB / BM, CKP / BN), 128>>>();
    softmax_kernel<<<NB / 8, 256>>>((float*)d_out);
}